// round 3
// baseline (speedup 1.0000x reference)
#include <cuda_runtime.h>
#include <math.h>

#define NHC 256
#define OC1 512
#define IC1 257
#define KW 5
#define BATCH 64
#define TMAX 4096
#define TOUT_MAX 2048

typedef unsigned long long ull;

// Scratch (device globals -- no allocation allowed)
__device__ float g_bufL[BATCH * NHC * TOUT_MAX];
__device__ float g_bufR[BATCH * NHC * TOUT_MAX];
__device__ float g_bufH0[BATCH * NHC * TOUT_MAX];
__device__ float g_bufH1[BATCH * NHC * TOUT_MAX];
__device__ float g_captured[BATCH * NHC];
// Duplicated-pair transposed weights: (w,w) at [(ic*KW+k)*OC + oc]
__device__ float2 g_w1T2[IC1 * KW * OC1];
__device__ float2 g_w2T2[NHC * KW * NHC];

__device__ __forceinline__ ull pack2(float lo, float hi) {
    ull r;
    asm("mov.b64 %0, {%1, %2};" : "=l"(r) : "f"(lo), "f"(hi));
    return r;
}
__device__ __forceinline__ ull fma2(ull a, ull b, ull c) {
    ull d;
    asm("fma.rn.f32x2 %0, %1, %2, %3;" : "=l"(d) : "l"(a), "l"(b), "l"(c));
    return d;
}
__device__ __forceinline__ void unpack2(ull v, float& lo, float& hi) {
    asm("mov.b64 {%0, %1}, %2;" : "=f"(lo), "=f"(hi) : "l"(v));
}

__device__ __forceinline__ int finish_depth(int n) {
    #pragma unroll 1
    for (int dd = 0; dd < 12; dd++) {
        n = (n - 1) / 2 + 1;
        if (n <= 1) return dd;
    }
    return 11;
}

// ---- weight transpose kernels (duplicate each w into a (w,w) float2) ----
__global__ void transpose_w1_kernel(const float* __restrict__ w1) {
    int idx = blockIdx.x * blockDim.x + threadIdx.x;
    int total = OC1 * IC1 * KW;
    if (idx < total) {
        int k  = idx % KW;
        int ic = (idx / KW) % IC1;
        int oc = idx / (KW * IC1);
        float w = w1[idx];
        g_w1T2[(ic * KW + k) * OC1 + oc] = make_float2(w, w);
    }
}
__global__ void transpose_w2_kernel(const float* __restrict__ w2) {
    int idx = blockIdx.x * blockDim.x + threadIdx.x;
    int total = NHC * NHC * KW;
    if (idx < total) {
        int k  = idx % KW;
        int ic = (idx / KW) % NHC;
        int oc = idx / (KW * NHC);
        float w = w2[idx];
        g_w2T2[(ic * KW + k) * NHC + oc] = make_float2(w, w);
    }
}

// conv1: OC=512 (threads), stride 2, K=5, pad 2. Deinterleaved even/odd smem
// rows (+1-shifted copies) so every f32x2 operand pair is one aligned LDS.64.
__global__ __launch_bounds__(512) void conv1_kernel(
    const float* __restrict__ h_ext, const int* __restrict__ N0,
    const float* __restrict__ b1,
    int d, int T_in, int T_out, float dval)
{
    const int b = blockIdx.y;
    const int tile = blockIdx.x;
    const int oc = threadIdx.x;              // 0..511
    const int t0 = tile * 16;
    const int pstart = 2 * t0 - 2;

    const float* hin = (d == 0) ? h_ext : (((d - 1) & 1) ? g_bufH1 : g_bufH0);
    const int n0 = N0[b];
    const int Ncur = (n0 + (1 << d) - 1) >> d;
    const int Nnew = (n0 + (2 << d) - 1) >> (d + 1);

    __shared__ __align__(16) float sxe [32][20];
    __shared__ __align__(16) float sxeS[32][20];
    __shared__ __align__(16) float sxo [32][20];
    __shared__ __align__(16) float sxoS[32][20];

    // scalar prologue: bias + depth channel
    float a[16];
    {
        float bias = b1[oc];
        float wd[5];
        #pragma unroll
        for (int k = 0; k < 5; k++) wd[k] = g_w1T2[(256 * KW + k) * OC1 + oc].x;
        #pragma unroll
        for (int t = 0; t < 16; t++) {
            float v = bias;
            #pragma unroll
            for (int k = 0; k < 5; k++) {
                int p = pstart + 2 * t + k;
                if (p >= 0 && p < Ncur) v += dval * wd[k];
            }
            a[t] = v;
        }
    }
    ull acc2[8];
    #pragma unroll
    for (int j = 0; j < 8; j++) acc2[j] = pack2(a[2*j], a[2*j+1]);

    for (int icc = 0; icc < NHC; icc += 32) {
        __syncthreads();
        for (int idx = threadIdx.x; idx < 32 * 36; idx += 512) {
            int ic = idx / 36, j = idx - ic * 36;
            int p = pstart + j;
            float v = 0.f;
            if (p >= 0 && p < Ncur)
                v = hin[((size_t)(b * NHC + icc + ic)) * T_in + p];
            int jh = j >> 1;
            if ((j & 1) == 0) {
                sxe[ic][jh] = v;
                if (jh) sxeS[ic][jh - 1] = v;
            } else {
                sxo[ic][jh] = v;
                if (jh) sxoS[ic][jh - 1] = v;
            }
        }
        __syncthreads();

        #pragma unroll 2
        for (int ic = 0; ic < 32; ic++) {
            const float2* wb = &g_w1T2[((icc + ic) * KW) * OC1 + oc];
            ull w0 = *(const ull*)(wb);
            ull w1v = *(const ull*)(wb + OC1);
            ull w2v = *(const ull*)(wb + 2 * OC1);
            ull w3v = *(const ull*)(wb + 3 * OC1);
            ull w4v = *(const ull*)(wb + 4 * OC1);

            ull P[9];
            #pragma unroll
            for (int j = 0; j < 9; j++) P[j] = *(const ull*)&sxe[ic][2*j];
            ull Q[8], R[8], S[8];
            #pragma unroll
            for (int j = 0; j < 8; j++) {
                Q[j] = *(const ull*)&sxeS[ic][2*j];
                R[j] = *(const ull*)&sxo [ic][2*j];
                S[j] = *(const ull*)&sxoS[ic][2*j];
            }
            #pragma unroll
            for (int j = 0; j < 8; j++) {
                acc2[j] = fma2(w0,  P[j],     acc2[j]);
                acc2[j] = fma2(w1v, R[j],     acc2[j]);
                acc2[j] = fma2(w2v, Q[j],     acc2[j]);
                acc2[j] = fma2(w3v, S[j],     acc2[j]);
                acc2[j] = fma2(w4v, P[j + 1], acc2[j]);
            }
        }
    }

    #pragma unroll
    for (int j = 0; j < 8; j++) unpack2(acc2[j], a[2*j], a[2*j+1]);

    #pragma unroll
    for (int t = 0; t < 16; t++) {
        int tg = t0 + t;
        if (tg < T_out) {
            if (oc < NHC) {
                g_bufL[((size_t)(b * NHC + oc)) * T_out + tg] = a[t];
            } else {
                float v = fmaxf(a[t], 0.f);
                if (tg >= Nnew) v = 0.f;
                g_bufR[((size_t)(b * NHC + oc - NHC)) * T_out + tg] = v;
            }
        }
    }
}

// conv2: 256x256, stride 1, K=5, pad 2; h = relu(l + conv2(r) + b2); captures h[:,:,0]
__global__ __launch_bounds__(256) void conv2_kernel(
    const int* __restrict__ N0,
    const float* __restrict__ b2, int d, int T_out)
{
    const int b = blockIdx.y;
    const int tile = blockIdx.x;
    const int oc = threadIdx.x;              // 0..255
    const int t0 = tile * 16;
    const int pstart = t0 - 2;
    float* hout = (d & 1) ? g_bufH1 : g_bufH0;

    __shared__ __align__(16) float sx [32][20];
    __shared__ __align__(16) float sxS[32][20];

    ull acc2[8];
    {
        float bias = b2[oc];
        ull bb = pack2(bias, bias);
        #pragma unroll
        for (int j = 0; j < 8; j++) acc2[j] = bb;
    }

    for (int icc = 0; icc < NHC; icc += 32) {
        __syncthreads();
        for (int idx = threadIdx.x; idx < 32 * 20; idx += 256) {
            int ic = idx / 20, j = idx - ic * 20;
            int p = pstart + j;
            float v = 0.f;
            if (p >= 0 && p < T_out)
                v = g_bufR[((size_t)(b * NHC + icc + ic)) * T_out + p];
            sx[ic][j] = v;
            if (j) sxS[ic][j - 1] = v;
        }
        __syncthreads();

        #pragma unroll 2
        for (int ic = 0; ic < 32; ic++) {
            const float2* wb = &g_w2T2[((icc + ic) * KW) * NHC + oc];
            ull w0 = *(const ull*)(wb);
            ull w1v = *(const ull*)(wb + NHC);
            ull w2v = *(const ull*)(wb + 2 * NHC);
            ull w3v = *(const ull*)(wb + 3 * NHC);
            ull w4v = *(const ull*)(wb + 4 * NHC);

            ull P[10];
            #pragma unroll
            for (int j = 0; j < 10; j++) P[j] = *(const ull*)&sx[ic][2*j];
            ull Q[9];
            #pragma unroll
            for (int j = 0; j < 9; j++) Q[j] = *(const ull*)&sxS[ic][2*j];

            #pragma unroll
            for (int j = 0; j < 8; j++) {
                acc2[j] = fma2(w0,  P[j],     acc2[j]);
                acc2[j] = fma2(w1v, Q[j],     acc2[j]);
                acc2[j] = fma2(w2v, P[j + 1], acc2[j]);
                acc2[j] = fma2(w3v, Q[j + 1], acc2[j]);
                acc2[j] = fma2(w4v, P[j + 2], acc2[j]);
            }
        }
    }

    float a[16];
    #pragma unroll
    for (int j = 0; j < 8; j++) unpack2(acc2[j], a[2*j], a[2*j+1]);

    #pragma unroll
    for (int t = 0; t < 16; t++) {
        int tg = t0 + t;
        if (tg < T_out) {
            size_t off = ((size_t)(b * NHC + oc)) * T_out + tg;
            float v = fmaxf(a[t] + g_bufL[off], 0.f);
            hout[off] = v;
            if (tg == 0) {
                if (finish_depth(N0[b]) == d)
                    g_captured[b * NHC + oc] = v;
            }
        }
    }
}

// Stable counting sort by finish depth, then gather captured rows.
__global__ void finalize_kernel(const int* __restrict__ N0, float* __restrict__ out)
{
    __shared__ int order[BATCH];
    if (threadIdx.x == 0) {
        int fd[BATCH];
        int cnt[13];
        for (int i = 0; i < 13; i++) cnt[i] = 0;
        for (int bb = 0; bb < BATCH; bb++) {
            fd[bb] = finish_depth(N0[bb]);
            cnt[fd[bb]]++;
        }
        int pos[13];
        int run = 0;
        for (int i = 0; i < 13; i++) { pos[i] = run; run += cnt[i]; }
        for (int bb = 0; bb < BATCH; bb++) {
            order[pos[fd[bb]]++] = bb;
        }
    }
    __syncthreads();
    for (int i = threadIdx.x; i < BATCH * NHC; i += blockDim.x) {
        int row = i >> 8, c = i & 255;
        out[i] = g_captured[order[row] * NHC + c];
    }
}

extern "C" void kernel_launch(void* const* d_in, const int* in_sizes, int n_in,
                              void* d_out, int out_size)
{
    const float* h  = (const float*)d_in[0];
    const int*   N0 = (const int*)d_in[1];
    const float* w1 = (const float*)d_in[2];
    const float* b1 = (const float*)d_in[3];
    const float* w2 = (const float*)d_in[4];
    const float* b2 = (const float*)d_in[5];

    {
        int tot1 = OC1 * IC1 * KW;
        transpose_w1_kernel<<<(tot1 + 255) / 256, 256>>>(w1);
        int tot2 = NHC * NHC * KW;
        transpose_w2_kernel<<<(tot2 + 255) / 256, 256>>>(w2);
    }

    for (int d = 0; d < 12; d++) {
        int T_in  = TMAX >> d;
        int T_out = T_in >> 1;
        int tiles = (T_out + 15) / 16;
        float dval = (float)log1p((double)d);
        conv1_kernel<<<dim3(tiles, BATCH), 512>>>(h, N0, b1, d, T_in, T_out, dval);
        conv2_kernel<<<dim3(tiles, BATCH), 256>>>(N0, b2, d, T_out);
    }
    finalize_kernel<<<1, 256>>>(N0, (float*)d_out);
}

// round 6
// speedup vs baseline: 1.0814x; 1.0814x over previous
#include <cuda_runtime.h>
#include <math.h>

#define NHC 256
#define OC1 512
#define IC1 257
#define KW 5
#define BATCH 64
#define TMAX 4096
#define TOUT_MAX 2048

typedef unsigned long long ull;

// Scratch (device globals -- no allocation allowed)
__device__ float g_bufL[BATCH * NHC * TOUT_MAX];
__device__ float g_bufR[BATCH * NHC * TOUT_MAX];
__device__ float g_bufH0[BATCH * NHC * TOUT_MAX];
__device__ float g_bufH1[BATCH * NHC * TOUT_MAX];
__device__ float g_captured[BATCH * NHC];
// Duplicated-pair transposed weights: (w,w) at [(ic*KW+k)*OC + oc]
__device__ float2 g_w1T2[IC1 * KW * OC1];
__device__ float2 g_w2T2[NHC * KW * NHC];

__device__ __forceinline__ ull pack2(float lo, float hi) {
    ull r;
    asm("mov.b64 %0, {%1, %2};" : "=l"(r) : "f"(lo), "f"(hi));
    return r;
}
__device__ __forceinline__ ull fma2(ull a, ull b, ull c) {
    ull d;
    asm("fma.rn.f32x2 %0, %1, %2, %3;" : "=l"(d) : "l"(a), "l"(b), "l"(c));
    return d;
}
__device__ __forceinline__ void unpack2(ull v, float& lo, float& hi) {
    asm("mov.b64 {%0, %1}, %2;" : "=f"(lo), "=f"(hi) : "l"(v));
}

__device__ __forceinline__ int finish_depth(int n) {
    #pragma unroll 1
    for (int dd = 0; dd < 12; dd++) {
        n = (n - 1) / 2 + 1;
        if (n <= 1) return dd;
    }
    return 11;
}

// ---- weight transpose kernels (duplicate each w into a (w,w) float2) ----
__global__ void transpose_w1_kernel(const float* __restrict__ w1) {
    int idx = blockIdx.x * blockDim.x + threadIdx.x;
    int total = OC1 * IC1 * KW;
    if (idx < total) {
        int k  = idx % KW;
        int ic = (idx / KW) % IC1;
        int oc = idx / (KW * IC1);
        float w = w1[idx];
        g_w1T2[(ic * KW + k) * OC1 + oc] = make_float2(w, w);
    }
}
__global__ void transpose_w2_kernel(const float* __restrict__ w2) {
    int idx = blockIdx.x * blockDim.x + threadIdx.x;
    int total = NHC * NHC * KW;
    if (idx < total) {
        int k  = idx % KW;
        int ic = (idx / KW) % NHC;
        int oc = idx / (KW * NHC);
        float w = w2[idx];
        g_w2T2[(ic * KW + k) * NHC + oc] = make_float2(w, w);
    }
}

// conv1: stride 2, K=5, pad 2. 256 threads, each handles oc and oc+256, 16 t-outputs.
// Deinterleaved even/odd smem (+1-shifted copies); pairs read via LDS.128.
__global__ __launch_bounds__(256) void conv1_kernel(
    const float* __restrict__ h_ext, const int* __restrict__ N0,
    const float* __restrict__ b1,
    int d, int T_in, int T_out, float dval)
{
    const int b = blockIdx.y;
    const int tile = blockIdx.x;
    const int oc = threadIdx.x;              // oc_a = oc, oc_b = oc + 256
    const int t0 = tile * 16;
    const int pstart = 2 * t0 - 2;

    const float* hin = (d == 0) ? h_ext : (((d - 1) & 1) ? g_bufH1 : g_bufH0);
    const int n0 = N0[b];
    const int Ncur = (n0 + (1 << d) - 1) >> d;
    const int Nnew = (n0 + (2 << d) - 1) >> (d + 1);

    __shared__ __align__(16) float sxe [32][20];
    __shared__ __align__(16) float sxeS[32][20];
    __shared__ __align__(16) float sxo [32][20];
    __shared__ __align__(16) float sxoS[32][20];

    // scalar prologue: bias + depth channel for both oc
    float aa[16], ab[16];
    {
        float biasA = b1[oc], biasB = b1[oc + 256];
        float wdA[5], wdB[5];
        #pragma unroll
        for (int k = 0; k < 5; k++) {
            wdA[k] = g_w1T2[(256 * KW + k) * OC1 + oc].x;
            wdB[k] = g_w1T2[(256 * KW + k) * OC1 + oc + 256].x;
        }
        #pragma unroll
        for (int t = 0; t < 16; t++) {
            float va = biasA, vb = biasB;
            #pragma unroll
            for (int k = 0; k < 5; k++) {
                int p = pstart + 2 * t + k;
                if (p >= 0 && p < Ncur) { va += dval * wdA[k]; vb += dval * wdB[k]; }
            }
            aa[t] = va; ab[t] = vb;
        }
    }
    ull accA[8], accB[8];
    #pragma unroll
    for (int j = 0; j < 8; j++) {
        accA[j] = pack2(aa[2*j], aa[2*j+1]);
        accB[j] = pack2(ab[2*j], ab[2*j+1]);
    }

    for (int icc = 0; icc < NHC; icc += 32) {
        __syncthreads();
        for (int idx = threadIdx.x; idx < 32 * 36; idx += 256) {
            int ic = idx / 36, j = idx - ic * 36;
            int p = pstart + j;
            float v = 0.f;
            if (p >= 0 && p < Ncur)
                v = hin[((size_t)(b * NHC + icc + ic)) * T_in + p];
            int jh = j >> 1;
            if ((j & 1) == 0) {
                sxe[ic][jh] = v;
                if (jh) sxeS[ic][jh - 1] = v;
            } else {
                sxo[ic][jh] = v;
                if (jh) sxoS[ic][jh - 1] = v;
            }
        }
        __syncthreads();

        #pragma unroll 2
        for (int ic = 0; ic < 32; ic++) {
            const float2* wb = &g_w1T2[((icc + ic) * KW) * OC1 + oc];

            // P: even pairs (xe[2j], xe[2j+1]), j=0..9 via 5x LDS.128
            ull P[10];
            {
                const ulonglong2* sp = reinterpret_cast<const ulonglong2*>(&sxe[ic][0]);
                #pragma unroll
                for (int q = 0; q < 5; q++) { ulonglong2 v = sp[q]; P[2*q] = v.x; P[2*q+1] = v.y; }
            }
            ull w0a = *(const ull*)(wb);
            ull w0b = *(const ull*)(wb + 256);
            ull w4a = *(const ull*)(wb + 4 * OC1);
            ull w4b = *(const ull*)(wb + 4 * OC1 + 256);
            #pragma unroll
            for (int j = 0; j < 8; j++) {
                accA[j] = fma2(w0a, P[j], accA[j]);
                accB[j] = fma2(w0b, P[j], accB[j]);
                accA[j] = fma2(w4a, P[j + 1], accA[j]);
                accB[j] = fma2(w4b, P[j + 1], accB[j]);
            }

            // R: odd pairs, j=0..7 via 4x LDS.128
            ull R[8];
            {
                const ulonglong2* sp = reinterpret_cast<const ulonglong2*>(&sxo[ic][0]);
                #pragma unroll
                for (int q = 0; q < 4; q++) { ulonglong2 v = sp[q]; R[2*q] = v.x; R[2*q+1] = v.y; }
            }
            ull w1a = *(const ull*)(wb + OC1);
            ull w1b = *(const ull*)(wb + OC1 + 256);
            #pragma unroll
            for (int j = 0; j < 8; j++) {
                accA[j] = fma2(w1a, R[j], accA[j]);
                accB[j] = fma2(w1b, R[j], accB[j]);
            }

            // Q: even-shifted pairs
            ull Q[8];
            {
                const ulonglong2* sp = reinterpret_cast<const ulonglong2*>(&sxeS[ic][0]);
                #pragma unroll
                for (int q = 0; q < 4; q++) { ulonglong2 v = sp[q]; Q[2*q] = v.x; Q[2*q+1] = v.y; }
            }
            ull w2a = *(const ull*)(wb + 2 * OC1);
            ull w2b = *(const ull*)(wb + 2 * OC1 + 256);
            #pragma unroll
            for (int j = 0; j < 8; j++) {
                accA[j] = fma2(w2a, Q[j], accA[j]);
                accB[j] = fma2(w2b, Q[j], accB[j]);
            }

            // S: odd-shifted pairs
            ull S[8];
            {
                const ulonglong2* sp = reinterpret_cast<const ulonglong2*>(&sxoS[ic][0]);
                #pragma unroll
                for (int q = 0; q < 4; q++) { ulonglong2 v = sp[q]; S[2*q] = v.x; S[2*q+1] = v.y; }
            }
            ull w3a = *(const ull*)(wb + 3 * OC1);
            ull w3b = *(const ull*)(wb + 3 * OC1 + 256);
            #pragma unroll
            for (int j = 0; j < 8; j++) {
                accA[j] = fma2(w3a, S[j], accA[j]);
                accB[j] = fma2(w3b, S[j], accB[j]);
            }
        }
    }

    #pragma unroll
    for (int j = 0; j < 8; j++) { unpack2(accA[j], aa[2*j], aa[2*j+1]); unpack2(accB[j], ab[2*j], ab[2*j+1]); }

    #pragma unroll
    for (int t = 0; t < 16; t++) {
        int tg = t0 + t;
        if (tg < T_out) {
            // oc_a < 256 -> L; oc_b >= 256 -> R (relu + mask)
            g_bufL[((size_t)(b * NHC + oc)) * T_out + tg] = aa[t];
            float v = fmaxf(ab[t], 0.f);
            if (tg >= Nnew) v = 0.f;
            g_bufR[((size_t)(b * NHC + oc)) * T_out + tg] = v;
        }
    }
}

// conv2: 256x256, stride 1, K=5, pad 2. 128 threads, each handles oc and oc+128.
__global__ __launch_bounds__(128) void conv2_kernel(
    const int* __restrict__ N0,
    const float* __restrict__ b2, int d, int T_out)
{
    const int b = blockIdx.y;
    const int tile = blockIdx.x;
    const int oc = threadIdx.x;              // oc_a = oc, oc_b = oc + 128
    const int t0 = tile * 16;
    const int pstart = t0 - 2;
    float* hout = (d & 1) ? g_bufH1 : g_bufH0;

    __shared__ __align__(16) float sx [32][20];
    __shared__ __align__(16) float sxS[32][20];

    ull accA[8], accB[8];
    {
        float biasA = b2[oc], biasB = b2[oc + 128];
        ull ba = pack2(biasA, biasA), bbp = pack2(biasB, biasB);
        #pragma unroll
        for (int j = 0; j < 8; j++) { accA[j] = ba; accB[j] = bbp; }
    }

    for (int icc = 0; icc < NHC; icc += 32) {
        __syncthreads();
        for (int idx = threadIdx.x; idx < 32 * 20; idx += 128) {
            int ic = idx / 20, j = idx - ic * 20;
            int p = pstart + j;
            float v = 0.f;
            if (p >= 0 && p < T_out)
                v = g_bufR[((size_t)(b * NHC + icc + ic)) * T_out + p];
            sx[ic][j] = v;
            if (j) sxS[ic][j - 1] = v;
        }
        __syncthreads();

        #pragma unroll 2
        for (int ic = 0; ic < 32; ic++) {
            const float2* wb = &g_w2T2[((icc + ic) * KW) * NHC + oc];

            ull P[10];
            {
                const ulonglong2* sp = reinterpret_cast<const ulonglong2*>(&sx[ic][0]);
                #pragma unroll
                for (int q = 0; q < 5; q++) { ulonglong2 v = sp[q]; P[2*q] = v.x; P[2*q+1] = v.y; }
            }
            ull w0a = *(const ull*)(wb);
            ull w0b = *(const ull*)(wb + 128);
            ull w2a = *(const ull*)(wb + 2 * NHC);
            ull w2b = *(const ull*)(wb + 2 * NHC + 128);
            ull w4a = *(const ull*)(wb + 4 * NHC);
            ull w4b = *(const ull*)(wb + 4 * NHC + 128);
            #pragma unroll
            for (int j = 0; j < 8; j++) {
                accA[j] = fma2(w0a, P[j],     accA[j]);
                accB[j] = fma2(w0b, P[j],     accB[j]);
                accA[j] = fma2(w2a, P[j + 1], accA[j]);
                accB[j] = fma2(w2b, P[j + 1], accB[j]);
                accA[j] = fma2(w4a, P[j + 2], accA[j]);
                accB[j] = fma2(w4b, P[j + 2], accB[j]);
            }

            ull Q[10];
            {
                const ulonglong2* sp = reinterpret_cast<const ulonglong2*>(&sxS[ic][0]);
                #pragma unroll
                for (int q = 0; q < 5; q++) { ulonglong2 v = sp[q]; Q[2*q] = v.x; Q[2*q+1] = v.y; }
            }
            ull w1a = *(const ull*)(wb + NHC);
            ull w1b = *(const ull*)(wb + NHC + 128);
            ull w3a = *(const ull*)(wb + 3 * NHC);
            ull w3b = *(const ull*)(wb + 3 * NHC + 128);
            #pragma unroll
            for (int j = 0; j < 8; j++) {
                accA[j] = fma2(w1a, Q[j],     accA[j]);
                accB[j] = fma2(w1b, Q[j],     accB[j]);
                accA[j] = fma2(w3a, Q[j + 1], accA[j]);
                accB[j] = fma2(w3b, Q[j + 1], accB[j]);
            }
        }
    }

    float aa[16], ab[16];
    #pragma unroll
    for (int j = 0; j < 8; j++) { unpack2(accA[j], aa[2*j], aa[2*j+1]); unpack2(accB[j], ab[2*j], ab[2*j+1]); }

    const int fdB = finish_depth(N0[b]);
    #pragma unroll
    for (int t = 0; t < 16; t++) {
        int tg = t0 + t;
        if (tg < T_out) {
            size_t offA = ((size_t)(b * NHC + oc)) * T_out + tg;
            size_t offB = ((size_t)(b * NHC + oc + 128)) * T_out + tg;
            float va = fmaxf(aa[t] + g_bufL[offA], 0.f);
            float vb = fmaxf(ab[t] + g_bufL[offB], 0.f);
            hout[offA] = va;
            hout[offB] = vb;
            if (tg == 0 && fdB == d) {
                g_captured[b * NHC + oc] = va;
                g_captured[b * NHC + oc + 128] = vb;
            }
        }
    }
}

// Stable counting sort by finish depth, then gather captured rows.
__global__ void finalize_kernel(const int* __restrict__ N0, float* __restrict__ out)
{
    __shared__ int order[BATCH];
    if (threadIdx.x == 0) {
        int fd[BATCH];
        int cnt[13];
        for (int i = 0; i < 13; i++) cnt[i] = 0;
        for (int bb = 0; bb < BATCH; bb++) {
            fd[bb] = finish_depth(N0[bb]);
            cnt[fd[bb]]++;
        }
        int pos[13];
        int run = 0;
        for (int i = 0; i < 13; i++) { pos[i] = run; run += cnt[i]; }
        for (int bb = 0; bb < BATCH; bb++) {
            order[pos[fd[bb]]++] = bb;
        }
    }
    __syncthreads();
    for (int i = threadIdx.x; i < BATCH * NHC; i += blockDim.x) {
        int row = i >> 8, c = i & 255;
        out[i] = g_captured[order[row] * NHC + c];
    }
}

extern "C" void kernel_launch(void* const* d_in, const int* in_sizes, int n_in,
                              void* d_out, int out_size)
{
    const float* h  = (const float*)d_in[0];
    const int*   N0 = (const int*)d_in[1];
    const float* w1 = (const float*)d_in[2];
    const float* b1 = (const float*)d_in[3];
    const float* w2 = (const float*)d_in[4];
    const float* b2 = (const float*)d_in[5];

    {
        int tot1 = OC1 * IC1 * KW;
        transpose_w1_kernel<<<(tot1 + 255) / 256, 256>>>(w1);
        int tot2 = NHC * NHC * KW;
        transpose_w2_kernel<<<(tot2 + 255) / 256, 256>>>(w2);
    }

    for (int d = 0; d < 12; d++) {
        int T_in  = TMAX >> d;
        int T_out = T_in >> 1;
        int tiles = (T_out + 15) / 16;
        float dval = (float)log1p((double)d);
        conv1_kernel<<<dim3(tiles, BATCH), 256>>>(h, N0, b1, d, T_in, T_out, dval);
        conv2_kernel<<<dim3(tiles, BATCH), 128>>>(N0, b2, d, T_out);
    }
    finalize_kernel<<<1, 256>>>(N0, (float*)d_out);
}

// round 8
// speedup vs baseline: 2.3183x; 2.1437x over previous
#include <cuda_runtime.h>
#include <cuda_bf16.h>
#include <math.h>

#define NHC 256
#define BATCH 64
#define TMAX 4096
#define TOUT_MAX 2048
#define KDIM 1280      // 256 ic * 5 taps
#define KC 64          // K per chunk
#define NCHUNK 20
#define NT 64          // t outputs per CTA
#define APAD 72        // padded row length in bf16 (144 B) -> conflict-free ldmatrix
#define ABLK (128 * APAD)

// ---------------- device global scratch ----------------
__device__ float g_bufL[BATCH*NHC*TOUT_MAX];
__device__ unsigned g_inplane[BATCH*NHC*TMAX];     // packed (hi<<16)|lo bf16
__device__ unsigned g_hplane0[BATCH*NHC*TOUT_MAX];
__device__ unsigned g_hplane1[BATCH*NHC*TOUT_MAX];
__device__ unsigned g_rplane [BATCH*NHC*TOUT_MAX];
__device__ float g_captured[BATCH*NHC];
// padded, pre-split weight blocks: [Mtile][chunk][128][APAD]
__device__ __align__(16) unsigned short g_a1hi[4*NCHUNK*ABLK];
__device__ __align__(16) unsigned short g_a1lo[4*NCHUNK*ABLK];
__device__ __align__(16) unsigned short g_a2hi[2*NCHUNK*ABLK];
__device__ __align__(16) unsigned short g_a2lo[2*NCHUNK*ABLK];

// ---------------- helpers ----------------
__device__ __forceinline__ unsigned smem_u32(const void* p) {
    unsigned a;
    asm("{ .reg .u64 t; cvta.to.shared.u64 t, %1; cvt.u32.u64 %0, t; }" : "=r"(a) : "l"(p));
    return a;
}
__device__ __forceinline__ unsigned pack_hl(float v) {
    __nv_bfloat16 h = __float2bfloat16(v);
    float hf = __bfloat162float(h);
    __nv_bfloat16 l = __float2bfloat16(v - hf);
    unsigned short hb = *reinterpret_cast<unsigned short*>(&h);
    unsigned short lb = *reinterpret_cast<unsigned short*>(&l);
    return ((unsigned)hb << 16) | (unsigned)lb;
}
__device__ __forceinline__ int finish_depth(int n) {
    #pragma unroll 1
    for (int dd = 0; dd < 12; dd++) {
        n = (n - 1) / 2 + 1;
        if (n <= 1) return dd;
    }
    return 11;
}
__device__ __forceinline__ void ldm4(unsigned* f, unsigned addr) {
    asm volatile("ldmatrix.sync.aligned.m8n8.x4.shared.b16 {%0,%1,%2,%3}, [%4];"
        : "=r"(f[0]), "=r"(f[1]), "=r"(f[2]), "=r"(f[3]) : "r"(addr));
}
__device__ __forceinline__ void ldm4t(unsigned* f, unsigned addr) {
    asm volatile("ldmatrix.sync.aligned.m8n8.x4.trans.shared.b16 {%0,%1,%2,%3}, [%4];"
        : "=r"(f[0]), "=r"(f[1]), "=r"(f[2]), "=r"(f[3]) : "r"(addr));
}
__device__ __forceinline__ void mma16816(float* c, const unsigned* a, const unsigned* b) {
    asm volatile("mma.sync.aligned.m16n8k16.row.col.f32.bf16.bf16.f32 "
        "{%0,%1,%2,%3}, {%4,%5,%6,%7}, {%8,%9}, {%0,%1,%2,%3};"
        : "+f"(c[0]), "+f"(c[1]), "+f"(c[2]), "+f"(c[3])
        : "r"(a[0]), "r"(a[1]), "r"(a[2]), "r"(a[3]), "r"(b[0]), "r"(b[1]));
}

// smem layout (bytes)
#define SM_AHI 0
#define SM_ALO 18432
#define SM_BHI 36864
#define SM_BLO 46080
#define SM_DYN 55296

// ---------------- prep kernels ----------------
__global__ void prep_input(const float* __restrict__ h) {
    long long idx = (long long)blockIdx.x * blockDim.x + threadIdx.x;
    if (idx < (long long)BATCH * NHC * TMAX)
        g_inplane[idx] = pack_hl(h[idx]);
}
__global__ void prep_w1(const float* __restrict__ w1) {
    int idx = blockIdx.x * blockDim.x + threadIdx.x;
    if (idx >= 512 * KDIM) return;
    int oc = idx / KDIM, k = idx % KDIM;
    int ic = k / 5, kk = k - 5 * ic;
    float w = w1[(oc * 257 + ic) * 5 + kk];
    __nv_bfloat16 h = __float2bfloat16(w);
    __nv_bfloat16 l = __float2bfloat16(w - __bfloat162float(h));
    int Mt = oc >> 7, m = oc & 127, ch = k >> 6, kl = k & 63;
    size_t off = (size_t)(Mt * NCHUNK + ch) * ABLK + m * APAD + kl;
    g_a1hi[off] = *reinterpret_cast<unsigned short*>(&h);
    g_a1lo[off] = *reinterpret_cast<unsigned short*>(&l);
}
__global__ void prep_w2(const float* __restrict__ w2) {
    int idx = blockIdx.x * blockDim.x + threadIdx.x;
    if (idx >= 256 * KDIM) return;
    int oc = idx / KDIM, k = idx % KDIM;
    int ic = k / 5, kk = k - 5 * ic;
    float w = w2[(oc * 256 + ic) * 5 + kk];
    __nv_bfloat16 h = __float2bfloat16(w);
    __nv_bfloat16 l = __float2bfloat16(w - __bfloat162float(h));
    int Mt = oc >> 7, m = oc & 127, ch = k >> 6, kl = k & 63;
    size_t off = (size_t)(Mt * NCHUNK + ch) * ABLK + m * APAD + kl;
    g_a2hi[off] = *reinterpret_cast<unsigned short*>(&h);
    g_a2lo[off] = *reinterpret_cast<unsigned short*>(&l);
}

// ---------------- conv1 (stride 2) ----------------
__global__ __launch_bounds__(256) void conv1_mma(
    const int* __restrict__ N0, const float* __restrict__ b1,
    const float* __restrict__ w1raw, const unsigned* __restrict__ plane,
    int d, int T_in, int T_out, float dval)
{
    extern __shared__ char smc[];
    const unsigned smb = smem_u32(smc);
    const int tid = threadIdx.x;
    const int b = blockIdx.z, Mtile = blockIdx.y, t0 = blockIdx.x * NT;

    const int n0 = N0[b];
    const int Ncur = (n0 + (1 << d) - 1) >> d;
    const int Nnew = (n0 + (2 << d) - 1) >> (d + 1);

    const int lane = tid & 31, q = lane >> 3, r = lane & 7;
    const int w = tid >> 5, wmi = w >> 1, wni = w & 1;

    // ldmatrix byte-address parts (relative to buffer base)
    unsigned aOff0 = (unsigned)((wmi * 32 + (q & 1) * 8 + r) * (APAD * 2) + (q >> 1) * 16);
    unsigned aOff1 = aOff0 + 16 * (APAD * 2);
    unsigned bOff0 = (unsigned)(((q & 1) * 8 + r) * (APAD * 2) + (wni * 32 + (q >> 1) * 8) * 2);
    unsigned bOff1 = bOff0 + 16 * 2;

    float acc[2][4][4];
    #pragma unroll
    for (int mt = 0; mt < 2; mt++)
        #pragma unroll
        for (int nt = 0; nt < 4; nt++)
            #pragma unroll
            for (int e = 0; e < 4; e++) acc[mt][nt][e] = 0.f;

    const int ablk0 = Mtile * NCHUNK;
    for (int ch = 0; ch < NCHUNK; ch++) {
        __syncthreads();
        // A copy (pre-padded, pre-split)
        {
            const uint4* sh = (const uint4*)(g_a1hi + (size_t)(ablk0 + ch) * ABLK);
            const uint4* sl = (const uint4*)(g_a1lo + (size_t)(ablk0 + ch) * ABLK);
            uint4* dh = (uint4*)(smc + SM_AHI);
            uint4* dl = (uint4*)(smc + SM_ALO);
            #pragma unroll
            for (int i = 0; i < 5; i++) {
                int ii = tid + 256 * i;
                if (ii < 1152) { dh[ii] = sh[ii]; dl[ii] = sl[ii]; }
            }
        }
        // B build: [k][n] rows, n contiguous (coalesced); stride-2 gather
        #pragma unroll
        for (int i = 0; i < 16; i++) {
            int idx = tid + 256 * i;
            int kl = idx >> 6, n = idx & 63;
            int kg = ch * KC + kl;
            int ic = kg / 5, kk = kg - 5 * ic;
            int p = 2 * (t0 + n) + kk - 2;
            unsigned v = 0;
            if (p >= 0 && p < Ncur)
                v = plane[((size_t)(b * NHC + ic)) * T_in + p];
            int so = kl * APAD + n;
            ((unsigned short*)(smc + SM_BHI))[so] = (unsigned short)(v >> 16);
            ((unsigned short*)(smc + SM_BLO))[so] = (unsigned short)(v & 0xFFFF);
        }
        __syncthreads();

        #pragma unroll
        for (int ks = 0; ks < 4; ks++) {
            const unsigned k2 = ks * 32;          // k0*2 bytes
            const unsigned kr = ks * 16 * (APAD * 2);
            unsigned ah0[4], ah1[4], al0[4], al1[4];
            ldm4(ah0, smb + SM_AHI + aOff0 + k2);
            ldm4(ah1, smb + SM_AHI + aOff1 + k2);
            ldm4(al0, smb + SM_ALO + aOff0 + k2);
            ldm4(al1, smb + SM_ALO + aOff1 + k2);
            unsigned bh[4][2], bl[4][2];
            {
                unsigned f[4];
                ldm4t(f, smb + SM_BHI + bOff0 + kr);
                bh[0][0] = f[0]; bh[0][1] = f[1]; bh[1][0] = f[2]; bh[1][1] = f[3];
                ldm4t(f, smb + SM_BHI + bOff1 + kr);
                bh[2][0] = f[0]; bh[2][1] = f[1]; bh[3][0] = f[2]; bh[3][1] = f[3];
                ldm4t(f, smb + SM_BLO + bOff0 + kr);
                bl[0][0] = f[0]; bl[0][1] = f[1]; bl[1][0] = f[2]; bl[1][1] = f[3];
                ldm4t(f, smb + SM_BLO + bOff1 + kr);
                bl[2][0] = f[0]; bl[2][1] = f[1]; bl[3][0] = f[2]; bl[3][1] = f[3];
            }
            #pragma unroll
            for (int mt = 0; mt < 2; mt++) {
                const unsigned* Ah = mt ? ah1 : ah0;
                const unsigned* Al = mt ? al1 : al0;
                #pragma unroll
                for (int nt = 0; nt < 4; nt++) {
                    mma16816(acc[mt][nt], Ah, bh[nt]);
                    mma16816(acc[mt][nt], Ah, bl[nt]);
                    mma16816(acc[mt][nt], Al, bh[nt]);
                }
            }
        }
    }

    // epilogue
    const int crow = lane >> 2, ccol = (lane & 3) * 2;
    #pragma unroll
    for (int mt = 0; mt < 2; mt++) {
        #pragma unroll
        for (int rh = 0; rh < 2; rh++) {
            int m = wmi * 32 + mt * 16 + rh * 8 + crow;
            int oc = Mtile * 128 + m;
            float bias = b1[oc];
            float wd[5];
            #pragma unroll
            for (int k = 0; k < 5; k++) wd[k] = w1raw[(oc * 257 + 256) * 5 + k];
            #pragma unroll
            for (int nt = 0; nt < 4; nt++) {
                #pragma unroll
                for (int e = 0; e < 2; e++) {
                    int tg = t0 + wni * 32 + nt * 8 + ccol + e;
                    if (tg < T_out) {
                        float v = acc[mt][nt][rh * 2 + e] + bias;
                        #pragma unroll
                        for (int k = 0; k < 5; k++) {
                            int p = 2 * tg + k - 2;
                            if (p >= 0 && p < Ncur) v += dval * wd[k];
                        }
                        if (Mtile < 2) {
                            g_bufL[((size_t)(b * NHC + oc)) * T_out + tg] = v;
                        } else {
                            v = fmaxf(v, 0.f);
                            if (tg >= Nnew) v = 0.f;
                            g_rplane[((size_t)(b * NHC + oc - 256)) * T_out + tg] = pack_hl(v);
                        }
                    }
                }
            }
        }
    }
}

// ---------------- conv2 (stride 1) ----------------
__global__ __launch_bounds__(256) void conv2_mma(
    const int* __restrict__ N0, const float* __restrict__ b2,
    int d, int T_out)
{
    extern __shared__ char smc[];
    const unsigned smb = smem_u32(smc);
    const int tid = threadIdx.x;
    const int b = blockIdx.z, Mtile = blockIdx.y, t0 = blockIdx.x * NT;
    unsigned* hout = (d & 1) ? g_hplane1 : g_hplane0;

    const int lane = tid & 31, q = lane >> 3, r = lane & 7;
    const int w = tid >> 5, wmi = w >> 1, wni = w & 1;

    unsigned aOff0 = (unsigned)((wmi * 32 + (q & 1) * 8 + r) * (APAD * 2) + (q >> 1) * 16);
    unsigned aOff1 = aOff0 + 16 * (APAD * 2);
    unsigned bOff0 = (unsigned)(((q & 1) * 8 + r) * (APAD * 2) + (wni * 32 + (q >> 1) * 8) * 2);
    unsigned bOff1 = bOff0 + 16 * 2;

    float acc[2][4][4];
    #pragma unroll
    for (int mt = 0; mt < 2; mt++)
        #pragma unroll
        for (int nt = 0; nt < 4; nt++)
            #pragma unroll
            for (int e = 0; e < 4; e++) acc[mt][nt][e] = 0.f;

    const int ablk0 = Mtile * NCHUNK;
    for (int ch = 0; ch < NCHUNK; ch++) {
        __syncthreads();
        {
            const uint4* sh = (const uint4*)(g_a2hi + (size_t)(ablk0 + ch) * ABLK);
            const uint4* sl = (const uint4*)(g_a2lo + (size_t)(ablk0 + ch) * ABLK);
            uint4* dh = (uint4*)(smc + SM_AHI);
            uint4* dl = (uint4*)(smc + SM_ALO);
            #pragma unroll
            for (int i = 0; i < 5; i++) {
                int ii = tid + 256 * i;
                if (ii < 1152) { dh[ii] = sh[ii]; dl[ii] = sl[ii]; }
            }
        }
        #pragma unroll
        for (int i = 0; i < 16; i++) {
            int idx = tid + 256 * i;
            int kl = idx >> 6, n = idx & 63;
            int kg = ch * KC + kl;
            int ic = kg / 5, kk = kg - 5 * ic;
            int p = t0 + n + kk - 2;
            unsigned v = 0;
            if (p >= 0 && p < T_out)
                v = g_rplane[((size_t)(b * NHC + ic)) * T_out + p];
            int so = kl * APAD + n;
            ((unsigned short*)(smc + SM_BHI))[so] = (unsigned short)(v >> 16);
            ((unsigned short*)(smc + SM_BLO))[so] = (unsigned short)(v & 0xFFFF);
        }
        __syncthreads();

        #pragma unroll
        for (int ks = 0; ks < 4; ks++) {
            const unsigned k2 = ks * 32;
            const unsigned kr = ks * 16 * (APAD * 2);
            unsigned ah0[4], ah1[4], al0[4], al1[4];
            ldm4(ah0, smb + SM_AHI + aOff0 + k2);
            ldm4(ah1, smb + SM_AHI + aOff1 + k2);
            ldm4(al0, smb + SM_ALO + aOff0 + k2);
            ldm4(al1, smb + SM_ALO + aOff1 + k2);
            unsigned bh[4][2], bl[4][2];
            {
                unsigned f[4];
                ldm4t(f, smb + SM_BHI + bOff0 + kr);
                bh[0][0] = f[0]; bh[0][1] = f[1]; bh[1][0] = f[2]; bh[1][1] = f[3];
                ldm4t(f, smb + SM_BHI + bOff1 + kr);
                bh[2][0] = f[0]; bh[2][1] = f[1]; bh[3][0] = f[2]; bh[3][1] = f[3];
                ldm4t(f, smb + SM_BLO + bOff0 + kr);
                bl[0][0] = f[0]; bl[0][1] = f[1]; bl[1][0] = f[2]; bl[1][1] = f[3];
                ldm4t(f, smb + SM_BLO + bOff1 + kr);
                bl[2][0] = f[0]; bl[2][1] = f[1]; bl[3][0] = f[2]; bl[3][1] = f[3];
            }
            #pragma unroll
            for (int mt = 0; mt < 2; mt++) {
                const unsigned* Ah = mt ? ah1 : ah0;
                const unsigned* Al = mt ? al1 : al0;
                #pragma unroll
                for (int nt = 0; nt < 4; nt++) {
                    mma16816(acc[mt][nt], Ah, bh[nt]);
                    mma16816(acc[mt][nt], Ah, bl[nt]);
                    mma16816(acc[mt][nt], Al, bh[nt]);
                }
            }
        }
    }

    const int crow = lane >> 2, ccol = (lane & 3) * 2;
    const int fd = finish_depth(N0[b]);
    #pragma unroll
    for (int mt = 0; mt < 2; mt++) {
        #pragma unroll
        for (int rh = 0; rh < 2; rh++) {
            int m = wmi * 32 + mt * 16 + rh * 8 + crow;
            int oc = Mtile * 128 + m;
            float bias = b2[oc];
            #pragma unroll
            for (int nt = 0; nt < 4; nt++) {
                #pragma unroll
                for (int e = 0; e < 2; e++) {
                    int tg = t0 + wni * 32 + nt * 8 + ccol + e;
                    if (tg < T_out) {
                        size_t off = ((size_t)(b * NHC + oc)) * T_out + tg;
                        float v = fmaxf(acc[mt][nt][rh * 2 + e] + bias + g_bufL[off], 0.f);
                        hout[off] = pack_hl(v);
                        if (tg == 0 && fd == d)
                            g_captured[b * NHC + oc] = v;
                    }
                }
            }
        }
    }
}

// ---------------- finalize ----------------
__global__ void finalize_kernel(const int* __restrict__ N0, float* __restrict__ out)
{
    __shared__ int order[BATCH];
    if (threadIdx.x == 0) {
        int fd[BATCH];
        int cnt[13];
        for (int i = 0; i < 13; i++) cnt[i] = 0;
        for (int bb = 0; bb < BATCH; bb++) {
            fd[bb] = finish_depth(N0[bb]);
            cnt[fd[bb]]++;
        }
        int pos[13];
        int run = 0;
        for (int i = 0; i < 13; i++) { pos[i] = run; run += cnt[i]; }
        for (int bb = 0; bb < BATCH; bb++) order[pos[fd[bb]]++] = bb;
    }
    __syncthreads();
    for (int i = threadIdx.x; i < BATCH * NHC; i += blockDim.x) {
        int row = i >> 8, c = i & 255;
        out[i] = g_captured[order[row] * NHC + c];
    }
}

// ---------------- launch ----------------
extern "C" void kernel_launch(void* const* d_in, const int* in_sizes, int n_in,
                              void* d_out, int out_size)
{
    const float* h  = (const float*)d_in[0];
    const int*   N0 = (const int*)d_in[1];
    const float* w1 = (const float*)d_in[2];
    const float* b1 = (const float*)d_in[3];
    const float* w2 = (const float*)d_in[4];
    const float* b2 = (const float*)d_in[5];

    cudaFuncSetAttribute(conv1_mma, cudaFuncAttributeMaxDynamicSharedMemorySize, SM_DYN);
    cudaFuncSetAttribute(conv2_mma, cudaFuncAttributeMaxDynamicSharedMemorySize, SM_DYN);

    {
        long long tot = (long long)BATCH * NHC * TMAX;
        prep_input<<<(int)((tot + 255) / 256), 256>>>(h);
        prep_w1<<<(512 * KDIM + 255) / 256, 256>>>(w1);
        prep_w2<<<(256 * KDIM + 255) / 256, 256>>>(w2);
    }

    unsigned* hp0; unsigned* hp1; unsigned* inp;
    cudaGetSymbolAddress((void**)&hp0, g_hplane0);
    cudaGetSymbolAddress((void**)&hp1, g_hplane1);
    cudaGetSymbolAddress((void**)&inp, g_inplane);

    for (int d = 0; d < 12; d++) {
        int T_in  = TMAX >> d;
        int T_out = T_in >> 1;
        int tiles = (T_out + NT - 1) / NT;
        float dval = (float)log1p((double)d);
        const unsigned* plane = (d == 0) ? inp : (((d - 1) & 1) ? hp1 : hp0);
        conv1_mma<<<dim3(tiles, 4, BATCH), 256, SM_DYN>>>(N0, b1, w1, plane, d, T_in, T_out, dval);
        conv2_mma<<<dim3(tiles, 2, BATCH), 256, SM_DYN>>>(N0, b2, d, T_out);
    }
    finalize_kernel<<<1, 256>>>(N0, (float*)d_out);
}

// round 9
// speedup vs baseline: 3.1543x; 1.3606x over previous
#include <cuda_runtime.h>
#include <cuda_bf16.h>
#include <math.h>

#define NHC 256
#define BATCH 64
#define TMAX 4096
#define TOUT_MAX 2048
#define KDIM 1280
#define KC 64
#define NCHUNK 20
#define NT 64
#define APAD 72
#define FRAG_PER_MT (NCHUNK*4*8*32)   // 20480 uint4 per Mtile

// ---------------- device global scratch ----------------
__device__ float g_bufL[BATCH*NHC*TOUT_MAX];
__device__ unsigned g_inplane[BATCH*NHC*TMAX];     // packed (hi<<16)|lo bf16
__device__ unsigned g_hplane0[BATCH*NHC*TOUT_MAX];
__device__ unsigned g_hplane1[BATCH*NHC*TOUT_MAX];
__device__ unsigned g_rplane [BATCH*NHC*TOUT_MAX];
__device__ float g_captured[BATCH*NHC];
__device__ float g_wdep[512*8];                    // wd[0..4], sum, pad
// A fragments in mma register order: [Mt][ch][ks][tile(8)][lane(32)] uint4
__device__ __align__(16) uint4 g_a1hiF[4*FRAG_PER_MT];
__device__ __align__(16) uint4 g_a1loF[4*FRAG_PER_MT];
__device__ __align__(16) uint4 g_a2hiF[2*FRAG_PER_MT];
__device__ __align__(16) uint4 g_a2loF[2*FRAG_PER_MT];

// ---------------- helpers ----------------
__device__ __forceinline__ unsigned smem_u32(const void* p) {
    unsigned a;
    asm("{ .reg .u64 t; cvta.to.shared.u64 t, %1; cvt.u32.u64 %0, t; }" : "=r"(a) : "l"(p));
    return a;
}
__device__ __forceinline__ unsigned pack_hl(float v) {
    __nv_bfloat16 h = __float2bfloat16(v);
    float hf = __bfloat162float(h);
    __nv_bfloat16 l = __float2bfloat16(v - hf);
    unsigned short hb = *reinterpret_cast<unsigned short*>(&h);
    unsigned short lb = *reinterpret_cast<unsigned short*>(&l);
    return ((unsigned)hb << 16) | (unsigned)lb;
}
__device__ __forceinline__ int finish_depth(int n) {
    #pragma unroll 1
    for (int dd = 0; dd < 12; dd++) {
        n = (n - 1) / 2 + 1;
        if (n <= 1) return dd;
    }
    return 11;
}
__device__ __forceinline__ void ldm4t(unsigned* f, unsigned addr) {
    asm volatile("ldmatrix.sync.aligned.m8n8.x4.trans.shared.b16 {%0,%1,%2,%3}, [%4];"
        : "=r"(f[0]), "=r"(f[1]), "=r"(f[2]), "=r"(f[3]) : "r"(addr));
}
__device__ __forceinline__ void mma16816(float* c, const unsigned* a, const unsigned* b) {
    asm volatile("mma.sync.aligned.m16n8k16.row.col.f32.bf16.bf16.f32 "
        "{%0,%1,%2,%3}, {%4,%5,%6,%7}, {%8,%9}, {%0,%1,%2,%3};"
        : "+f"(c[0]), "+f"(c[1]), "+f"(c[2]), "+f"(c[3])
        : "r"(a[0]), "r"(a[1]), "r"(a[2]), "r"(a[3]), "r"(b[0]), "r"(b[1]));
}

#define SM_STAGE 18432       // 9216 hi + 9216 lo per stage
#define SM_DYN   36864

// ---------------- prep kernels ----------------
__global__ void prep_input(const float* __restrict__ h) {
    long long idx = (long long)blockIdx.x * blockDim.x + threadIdx.x;
    if (idx < (long long)BATCH * NHC * TMAX)
        g_inplane[idx] = pack_hl(h[idx]);
}
__global__ void prep_w1(const float* __restrict__ w1) {
    int idx = blockIdx.x * blockDim.x + threadIdx.x;
    if (idx >= 4 * FRAG_PER_MT) return;
    int lane = idx & 31;
    int tile = (idx >> 5) & 7;
    int ks   = (idx >> 8) & 3;
    int rest = idx >> 10;          // Mt*20 + ch
    int ch = rest % NCHUNK;
    int Mt = rest / NCHUNK;
    int r0 = tile * 16 + (lane >> 2);
    int c0 = ks * 16 + (lane & 3) * 2;
    unsigned hi[4], lo[4];
    #pragma unroll
    for (int e = 0; e < 4; e++) {
        int rr = r0 + (e & 1) * 8;
        int cc = c0 + (e >> 1) * 8;
        unsigned h2 = 0, l2 = 0;
        #pragma unroll
        for (int j = 0; j < 2; j++) {
            int kg = ch * KC + cc + j;
            int ic = kg / 5, kk = kg - 5 * ic;
            int oc = Mt * 128 + rr;
            float w = w1[(oc * 257 + ic) * 5 + kk];
            __nv_bfloat16 h = __float2bfloat16(w);
            __nv_bfloat16 l = __float2bfloat16(w - __bfloat162float(h));
            h2 |= ((unsigned)*(unsigned short*)&h) << (16 * j);
            l2 |= ((unsigned)*(unsigned short*)&l) << (16 * j);
        }
        hi[e] = h2; lo[e] = l2;
    }
    g_a1hiF[idx] = make_uint4(hi[0], hi[1], hi[2], hi[3]);
    g_a1loF[idx] = make_uint4(lo[0], lo[1], lo[2], lo[3]);
}
__global__ void prep_w2(const float* __restrict__ w2) {
    int idx = blockIdx.x * blockDim.x + threadIdx.x;
    if (idx >= 2 * FRAG_PER_MT) return;
    int lane = idx & 31;
    int tile = (idx >> 5) & 7;
    int ks   = (idx >> 8) & 3;
    int rest = idx >> 10;
    int ch = rest % NCHUNK;
    int Mt = rest / NCHUNK;
    int r0 = tile * 16 + (lane >> 2);
    int c0 = ks * 16 + (lane & 3) * 2;
    unsigned hi[4], lo[4];
    #pragma unroll
    for (int e = 0; e < 4; e++) {
        int rr = r0 + (e & 1) * 8;
        int cc = c0 + (e >> 1) * 8;
        unsigned h2 = 0, l2 = 0;
        #pragma unroll
        for (int j = 0; j < 2; j++) {
            int kg = ch * KC + cc + j;
            int ic = kg / 5, kk = kg - 5 * ic;
            int oc = Mt * 128 + rr;
            float w = w2[(oc * 256 + ic) * 5 + kk];
            __nv_bfloat16 h = __float2bfloat16(w);
            __nv_bfloat16 l = __float2bfloat16(w - __bfloat162float(h));
            h2 |= ((unsigned)*(unsigned short*)&h) << (16 * j);
            l2 |= ((unsigned)*(unsigned short*)&l) << (16 * j);
        }
        hi[e] = h2; lo[e] = l2;
    }
    g_a2hiF[idx] = make_uint4(hi[0], hi[1], hi[2], hi[3]);
    g_a2loF[idx] = make_uint4(lo[0], lo[1], lo[2], lo[3]);
}
__global__ void prep_wdep(const float* __restrict__ w1) {
    int oc = blockIdx.x * blockDim.x + threadIdx.x;
    if (oc >= 512) return;
    float s = 0.f;
    #pragma unroll
    for (int k = 0; k < 5; k++) {
        float w = w1[(oc * 257 + 256) * 5 + k];
        g_wdep[oc * 8 + k] = w;
        s += w;
    }
    g_wdep[oc * 8 + 5] = s;
    g_wdep[oc * 8 + 6] = 0.f;
    g_wdep[oc * 8 + 7] = 0.f;
}

// ---------------- conv1 (stride 2) ----------------
__global__ __launch_bounds__(256) void conv1_mma(
    const int* __restrict__ N0, const float* __restrict__ b1,
    const unsigned* __restrict__ plane,
    int d, int T_in, int T_out, float dval)
{
    extern __shared__ char smc[];
    const unsigned smb = smem_u32(smc);
    const int tid = threadIdx.x;
    const int b = blockIdx.z, Mtile = blockIdx.y, t0 = blockIdx.x * NT;
    const int lane = tid & 31, q = lane >> 3, r = lane & 7;
    const int w8 = tid >> 5, wmi = w8 >> 1, wni = w8 & 1;

    const int n0v = N0[b];
    const int Ncur = (n0v + (1 << d) - 1) >> d;
    const int Nnew = (n0v + (2 << d) - 1) >> (d + 1);

    const unsigned bOff0 = (unsigned)(((q & 1) * 8 + r) * (APAD * 2) + (wni * 32 + (q >> 1) * 8) * 2);
    const unsigned bOff1 = bOff0 + 32;

    float acc[2][4][4];
    #pragma unroll
    for (int mt = 0; mt < 2; mt++)
        #pragma unroll
        for (int nt = 0; nt < 4; nt++)
            #pragma unroll
            for (int e = 0; e < 4; e++) acc[mt][nt][e] = 0.f;

    const int pbase = 2 * (t0 + 2 * lane) - 2;
    unsigned v[16];

    auto bload = [&](int ch) {
        #pragma unroll
        for (int i = 0; i < 8; i++) {
            int kl = i * 8 + w8;
            int kg = ch * KC + kl;
            int ic = kg / 5, kk = kg - 5 * ic;
            unsigned base = (unsigned)(b * NHC + ic) * (unsigned)T_in;
            int p0 = pbase + kk;
            int p1 = p0 + 2;
            v[2 * i]     = (p0 >= 0 && p0 < Ncur) ? plane[base + p0] : 0u;
            v[2 * i + 1] = (p1 >= 0 && p1 < Ncur) ? plane[base + p1] : 0u;
        }
    };
    auto bstore = [&](int st) {
        unsigned* bh = (unsigned*)(smc + st * SM_STAGE);
        unsigned* bl = bh + 2304;
        #pragma unroll
        for (int i = 0; i < 8; i++) {
            int kl = i * 8 + w8;
            int so = (kl * APAD + 2 * lane) >> 1;
            unsigned v0 = v[2 * i], v1 = v[2 * i + 1];
            bh[so] = (v0 >> 16) | (v1 & 0xFFFF0000u);
            bl[so] = (v0 & 0xFFFFu) | (v1 << 16);
        }
    };

    const uint4* Ah0 = g_a1hiF + (size_t)Mtile * FRAG_PER_MT;
    const uint4* Al0 = g_a1loF + (size_t)Mtile * FRAG_PER_MT;

    bload(0);
    for (int ch = 0; ch < NCHUNK; ch++) {
        const int st = ch & 1;
        bstore(st);
        __syncthreads();
        if (ch + 1 < NCHUNK) bload(ch + 1);
        const unsigned bbase = smb + st * SM_STAGE;
        #pragma unroll
        for (int ks = 0; ks < 4; ks++) {
            const int fidx = ((ch * 4 + ks) * 8 + wmi * 2) * 32 + lane;
            uint4 fh0 = Ah0[fidx];
            uint4 fh1 = Ah0[fidx + 32];
            uint4 fl0 = Al0[fidx];
            uint4 fl1 = Al0[fidx + 32];
            const unsigned kr = (unsigned)(ks * 16 * (APAD * 2));
            unsigned bhf[4][2], blf[4][2], f[4];
            ldm4t(f, bbase + bOff0 + kr);
            bhf[0][0] = f[0]; bhf[0][1] = f[1]; bhf[1][0] = f[2]; bhf[1][1] = f[3];
            ldm4t(f, bbase + bOff1 + kr);
            bhf[2][0] = f[0]; bhf[2][1] = f[1]; bhf[3][0] = f[2]; bhf[3][1] = f[3];
            ldm4t(f, bbase + 9216 + bOff0 + kr);
            blf[0][0] = f[0]; blf[0][1] = f[1]; blf[1][0] = f[2]; blf[1][1] = f[3];
            ldm4t(f, bbase + 9216 + bOff1 + kr);
            blf[2][0] = f[0]; blf[2][1] = f[1]; blf[3][0] = f[2]; blf[3][1] = f[3];
            const unsigned* AH[2] = {(const unsigned*)&fh0, (const unsigned*)&fh1};
            const unsigned* AL[2] = {(const unsigned*)&fl0, (const unsigned*)&fl1};
            #pragma unroll
            for (int mt = 0; mt < 2; mt++) {
                #pragma unroll
                for (int nt = 0; nt < 4; nt++) {
                    mma16816(acc[mt][nt], AH[mt], bhf[nt]);
                    mma16816(acc[mt][nt], AH[mt], blf[nt]);
                    mma16816(acc[mt][nt], AL[mt], bhf[nt]);
                }
            }
        }
    }

    // epilogue
    const int crow = lane >> 2, ccol = (lane & 3) * 2;
    const bool dep = (dval != 0.f);
    #pragma unroll
    for (int mt = 0; mt < 2; mt++) {
        #pragma unroll
        for (int rh = 0; rh < 2; rh++) {
            const int oc = Mtile * 128 + wmi * 32 + mt * 16 + rh * 8 + crow;
            const float bias = b1[oc];
            float wd[5], sfull = 0.f;
            if (dep) {
                float4 wA = *(const float4*)&g_wdep[oc * 8];
                float2 wB = *(const float2*)&g_wdep[oc * 8 + 4];
                wd[0] = wA.x; wd[1] = wA.y; wd[2] = wA.z; wd[3] = wA.w; wd[4] = wB.x;
                sfull = wB.y;
            }
            auto dcor = [&](int t) -> float {
                if (t >= 1 && 2 * t + 2 < Ncur) return sfull;
                float s = 0.f;
                #pragma unroll
                for (int k = 0; k < 5; k++) {
                    int p = 2 * t + k - 2;
                    if (p >= 0 && p < Ncur) s += wd[k];
                }
                return s;
            };
            #pragma unroll
            for (int nt = 0; nt < 4; nt++) {
                const int tg = t0 + wni * 32 + nt * 8 + ccol;
                float c0v = acc[mt][nt][rh * 2 + 0] + bias;
                float c1v = acc[mt][nt][rh * 2 + 1] + bias;
                if (dep) {
                    c0v += dval * dcor(tg);
                    c1v += dval * dcor(tg + 1);
                }
                if (Mtile < 2) {
                    size_t off = (size_t)(b * NHC + oc) * T_out + tg;
                    if (tg + 1 < T_out)      *(float2*)&g_bufL[off] = make_float2(c0v, c1v);
                    else if (tg < T_out)     g_bufL[off] = c0v;
                } else {
                    float r0v = fmaxf(c0v, 0.f); if (tg     >= Nnew) r0v = 0.f;
                    float r1v = fmaxf(c1v, 0.f); if (tg + 1 >= Nnew) r1v = 0.f;
                    size_t off = (size_t)(b * NHC + oc - 256) * T_out + tg;
                    if (tg + 1 < T_out)      *(uint2*)&g_rplane[off] = make_uint2(pack_hl(r0v), pack_hl(r1v));
                    else if (tg < T_out)     g_rplane[off] = pack_hl(r0v);
                }
            }
        }
    }
}

// ---------------- conv2 (stride 1) ----------------
__global__ __launch_bounds__(256) void conv2_mma(
    const int* __restrict__ N0, const float* __restrict__ b2,
    int d, int T_out)
{
    extern __shared__ char smc[];
    const unsigned smb = smem_u32(smc);
    const int tid = threadIdx.x;
    const int b = blockIdx.z, Mtile = blockIdx.y, t0 = blockIdx.x * NT;
    const int lane = tid & 31, q = lane >> 3, r = lane & 7;
    const int w8 = tid >> 5, wmi = w8 >> 1, wni = w8 & 1;
    unsigned* hout = (d & 1) ? g_hplane1 : g_hplane0;

    const unsigned bOff0 = (unsigned)(((q & 1) * 8 + r) * (APAD * 2) + (wni * 32 + (q >> 1) * 8) * 2);
    const unsigned bOff1 = bOff0 + 32;

    float acc[2][4][4];
    #pragma unroll
    for (int mt = 0; mt < 2; mt++)
        #pragma unroll
        for (int nt = 0; nt < 4; nt++)
            #pragma unroll
            for (int e = 0; e < 4; e++) acc[mt][nt][e] = 0.f;

    const int pbase = t0 + 2 * lane - 2;
    unsigned v[16];

    auto bload = [&](int ch) {
        #pragma unroll
        for (int i = 0; i < 8; i++) {
            int kl = i * 8 + w8;
            int kg = ch * KC + kl;
            int ic = kg / 5, kk = kg - 5 * ic;
            unsigned base = (unsigned)(b * NHC + ic) * (unsigned)T_out;
            int p0 = pbase + kk;
            int p1 = p0 + 1;
            v[2 * i]     = (p0 >= 0 && p0 < T_out) ? g_rplane[base + p0] : 0u;
            v[2 * i + 1] = (p1 >= 0 && p1 < T_out) ? g_rplane[base + p1] : 0u;
        }
    };
    auto bstore = [&](int st) {
        unsigned* bh = (unsigned*)(smc + st * SM_STAGE);
        unsigned* bl = bh + 2304;
        #pragma unroll
        for (int i = 0; i < 8; i++) {
            int kl = i * 8 + w8;
            int so = (kl * APAD + 2 * lane) >> 1;
            unsigned v0 = v[2 * i], v1 = v[2 * i + 1];
            bh[so] = (v0 >> 16) | (v1 & 0xFFFF0000u);
            bl[so] = (v0 & 0xFFFFu) | (v1 << 16);
        }
    };

    const uint4* Ah0 = g_a2hiF + (size_t)Mtile * FRAG_PER_MT;
    const uint4* Al0 = g_a2loF + (size_t)Mtile * FRAG_PER_MT;

    bload(0);
    for (int ch = 0; ch < NCHUNK; ch++) {
        const int st = ch & 1;
        bstore(st);
        __syncthreads();
        if (ch + 1 < NCHUNK) bload(ch + 1);
        const unsigned bbase = smb + st * SM_STAGE;
        #pragma unroll
        for (int ks = 0; ks < 4; ks++) {
            const int fidx = ((ch * 4 + ks) * 8 + wmi * 2) * 32 + lane;
            uint4 fh0 = Ah0[fidx];
            uint4 fh1 = Ah0[fidx + 32];
            uint4 fl0 = Al0[fidx];
            uint4 fl1 = Al0[fidx + 32];
            const unsigned kr = (unsigned)(ks * 16 * (APAD * 2));
            unsigned bhf[4][2], blf[4][2], f[4];
            ldm4t(f, bbase + bOff0 + kr);
            bhf[0][0] = f[0]; bhf[0][1] = f[1]; bhf[1][0] = f[2]; bhf[1][1] = f[3];
            ldm4t(f, bbase + bOff1 + kr);
            bhf[2][0] = f[0]; bhf[2][1] = f[1]; bhf[3][0] = f[2]; bhf[3][1] = f[3];
            ldm4t(f, bbase + 9216 + bOff0 + kr);
            blf[0][0] = f[0]; blf[0][1] = f[1]; blf[1][0] = f[2]; blf[1][1] = f[3];
            ldm4t(f, bbase + 9216 + bOff1 + kr);
            blf[2][0] = f[0]; blf[2][1] = f[1]; blf[3][0] = f[2]; blf[3][1] = f[3];
            const unsigned* AH[2] = {(const unsigned*)&fh0, (const unsigned*)&fh1};
            const unsigned* AL[2] = {(const unsigned*)&fl0, (const unsigned*)&fl1};
            #pragma unroll
            for (int mt = 0; mt < 2; mt++) {
                #pragma unroll
                for (int nt = 0; nt < 4; nt++) {
                    mma16816(acc[mt][nt], AH[mt], bhf[nt]);
                    mma16816(acc[mt][nt], AH[mt], blf[nt]);
                    mma16816(acc[mt][nt], AL[mt], bhf[nt]);
                }
            }
        }
    }

    const int crow = lane >> 2, ccol = (lane & 3) * 2;
    const int fd = finish_depth(N0[b]);
    #pragma unroll
    for (int mt = 0; mt < 2; mt++) {
        #pragma unroll
        for (int rh = 0; rh < 2; rh++) {
            const int oc = Mtile * 128 + wmi * 32 + mt * 16 + rh * 8 + crow;
            const float bias = b2[oc];
            #pragma unroll
            for (int nt = 0; nt < 4; nt++) {
                const int tg = t0 + wni * 32 + nt * 8 + ccol;
                const float c0v = acc[mt][nt][rh * 2 + 0] + bias;
                const float c1v = acc[mt][nt][rh * 2 + 1] + bias;
                size_t off = (size_t)(b * NHC + oc) * T_out + tg;
                if (tg + 1 < T_out) {
                    float2 L = *(const float2*)&g_bufL[off];
                    float v0 = fmaxf(c0v + L.x, 0.f);
                    float v1 = fmaxf(c1v + L.y, 0.f);
                    *(uint2*)&hout[off] = make_uint2(pack_hl(v0), pack_hl(v1));
                    if (tg == 0 && fd == d) g_captured[b * NHC + oc] = v0;
                } else if (tg < T_out) {
                    float v0 = fmaxf(c0v + g_bufL[off], 0.f);
                    hout[off] = pack_hl(v0);
                    if (tg == 0 && fd == d) g_captured[b * NHC + oc] = v0;
                }
            }
        }
    }
}

// ---------------- finalize ----------------
__global__ void finalize_kernel(const int* __restrict__ N0, float* __restrict__ out)
{
    __shared__ int order[BATCH];
    if (threadIdx.x == 0) {
        int fd[BATCH];
        int cnt[13];
        for (int i = 0; i < 13; i++) cnt[i] = 0;
        for (int bb = 0; bb < BATCH; bb++) {
            fd[bb] = finish_depth(N0[bb]);
            cnt[fd[bb]]++;
        }
        int pos[13];
        int run = 0;
        for (int i = 0; i < 13; i++) { pos[i] = run; run += cnt[i]; }
        for (int bb = 0; bb < BATCH; bb++) order[pos[fd[bb]]++] = bb;
    }
    __syncthreads();
    for (int i = threadIdx.x; i < BATCH * NHC; i += blockDim.x) {
        int row = i >> 8, c = i & 255;
        out[i] = g_captured[order[row] * NHC + c];
    }
}

// ---------------- launch ----------------
extern "C" void kernel_launch(void* const* d_in, const int* in_sizes, int n_in,
                              void* d_out, int out_size)
{
    const float* h  = (const float*)d_in[0];
    const int*   N0 = (const int*)d_in[1];
    const float* w1 = (const float*)d_in[2];
    const float* b1 = (const float*)d_in[3];
    const float* w2 = (const float*)d_in[4];
    const float* b2 = (const float*)d_in[5];

    cudaFuncSetAttribute(conv1_mma, cudaFuncAttributeMaxDynamicSharedMemorySize, SM_DYN);
    cudaFuncSetAttribute(conv2_mma, cudaFuncAttributeMaxDynamicSharedMemorySize, SM_DYN);

    {
        long long tot = (long long)BATCH * NHC * TMAX;
        prep_input<<<(int)((tot + 255) / 256), 256>>>(h);
        prep_w1<<<(4 * FRAG_PER_MT + 255) / 256, 256>>>(w1);
        prep_w2<<<(2 * FRAG_PER_MT + 255) / 256, 256>>>(w2);
        prep_wdep<<<2, 256>>>(w1);
    }

    unsigned* hp0; unsigned* hp1; unsigned* inp;
    cudaGetSymbolAddress((void**)&hp0, g_hplane0);
    cudaGetSymbolAddress((void**)&hp1, g_hplane1);
    cudaGetSymbolAddress((void**)&inp, g_inplane);

    for (int d = 0; d < 12; d++) {
        int T_in  = TMAX >> d;
        int T_out = T_in >> 1;
        int tiles = (T_out + NT - 1) / NT;
        float dval = (float)log1p((double)d);
        const unsigned* plane = (d == 0) ? inp : (((d - 1) & 1) ? hp1 : hp0);
        conv1_mma<<<dim3(tiles, 4, BATCH), 256, SM_DYN>>>(N0, b1, plane, d, T_in, T_out, dval);
        conv2_mma<<<dim3(tiles, 2, BATCH), 256, SM_DYN>>>(N0, b2, d, T_out);
    }
    finalize_kernel<<<1, 256>>>(N0, (float*)d_out);
}